// round 12
// baseline (speedup 1.0000x reference)
#include <cuda_runtime.h>
#include <stdint.h>

#define NUM_CLASSES 10000
#define FEATURE_DIM 2048
#define BATCH 512
#define TPB 256
#define NTOT ((size_t)NUM_CLASSES * FEATURE_DIM)
// ALPHA = 0.5 exactly -> powers of two via ldexpf

__device__ float g_part[BATCH];   // per-slot loss partials (all written every launch)
__device__ int   g_ctr = 0;       // completion counter; reducer resets to 0

// ---------------------------------------------------------------------------
// Owner kernel (runs AFTER the bulk memcpy has copied every row).
// Block b (0..511): decodes labels, collects matches of l = lab[b]; if b is the
// minimum batch index with that label it overwrites row l with the closed-form
// sequential EMA  new_c = 2^-k*c + sum_r 2^-(k-r)*f_r  (batch order, ALPHA=0.5)
// and computes that class's loss partial vs the ORIGINAL center row.
// Non-owners write partial 0. Last finishing block sums the 512 partials in
// fixed order -> loss_out[0]; resets g_ctr (graph-replay safe, deterministic).
// ---------------------------------------------------------------------------
__global__ void __launch_bounds__(TPB)
owner_kernel(const float* __restrict__ features,
             const float* __restrict__ centers,
             float* __restrict__ out_centers,
             float* __restrict__ loss_out,
             const int* __restrict__ labels_words) {
    __shared__ int   s_lab[BATCH];
    __shared__ int   s_not64;
    __shared__ int   s_match[BATCH];
    __shared__ float s_w[BATCH];
    __shared__ int   s_cnt;
    __shared__ float s_red[TPB / 32];
    __shared__ int   s_last;

    const int tid = threadIdx.x;
    const int b   = blockIdx.x;

    // ---- label decode (int64 vs int32 probe); each thread covers 2 indices ----
    int i0 = tid, i1 = tid + TPB;
    int w0lo = __ldg(labels_words + 2 * i0);
    int w0hi = __ldg(labels_words + 2 * i0 + 1);
    int w1lo = __ldg(labels_words + 2 * i1);
    int w1hi = __ldg(labels_words + 2 * i1 + 1);
    if (tid == 0) { s_not64 = 0; s_cnt = 0; }
    __syncthreads();
    if (w0hi != 0 || w0lo < 0 || w0lo >= NUM_CLASSES ||
        w1hi != 0 || w1lo < 0 || w1lo >= NUM_CLASSES)
        s_not64 = 1;                                   // benign race
    __syncthreads();
    if (s_not64) {
        s_lab[i0] = __ldg(labels_words + i0);
        s_lab[i1] = __ldg(labels_words + i1);
    } else {
        s_lab[i0] = w0lo;
        s_lab[i1] = w1lo;
    }
    __syncthreads();

    const int l = s_lab[b];
    for (int j = tid; j < BATCH; j += TPB)
        if (s_lab[j] == l) s_match[atomicAdd(&s_cnt, 1)] = j;
    __syncthreads();
    const int k = s_cnt;
    if (tid == 0) {   // restore batch order + EMA weights
        for (int a = 1; a < k; a++) {
            int v = s_match[a], c = a - 1;
            while (c >= 0 && s_match[c] > v) { s_match[c + 1] = s_match[c]; c--; }
            s_match[c + 1] = v;
        }
        for (int r = 0; r < k; r++) s_w[r] = ldexpf(1.0f, -(k - r));
    }
    __syncthreads();

    const bool owner = (s_match[0] == b);   // uniform across block
    float total = 0.0f;
    if (owner) {
        const float* crow = centers     + (size_t)l * FEATURE_DIM;
        float*       orow = out_centers + (size_t)l * FEATURE_DIM;
        const float  decay = ldexpf(1.0f, -k);
        float acc = 0.0f;
        #pragma unroll
        for (int s = 0; s < FEATURE_DIM / TPB; s++) {
            int c = tid + s * TPB;
            float cv = __ldg(crow + c);
            float nv = cv * decay;
            for (int r = 0; r < k; r++) {
                float f = __ldg(features + (size_t)s_match[r] * FEATURE_DIM + c);
                nv = fmaf(s_w[r], f, nv);
                float d = f - cv;                // loss vs ORIGINAL center
                acc = fmaf(d, d, acc);
            }
            orow[c] = nv;                        // overwrites memcpy'd copy
        }
        #pragma unroll
        for (int o = 16; o; o >>= 1) acc += __shfl_xor_sync(0xffffffffu, acc, o);
        if ((tid & 31) == 0) s_red[tid >> 5] = acc;
        __syncthreads();
        if (tid == 0) {
            float a2 = 0.0f;
            #pragma unroll
            for (int w = 0; w < TPB / 32; w++) a2 += s_red[w];
            total = a2 * (1.0f / ((float)BATCH * (float)FEATURE_DIM));
        }
    }
    if (tid == 0) g_part[b] = owner ? total : 0.0f;

    // ---- tail: last-block deterministic loss reduction ----
    __threadfence();
    __syncthreads();
    if (tid == 0) {
        int old = atomicAdd(&g_ctr, 1);
        s_last = (old == BATCH - 1) ? 1 : 0;
    }
    __syncthreads();
    if (s_last) {
        float a = 0.0f;
        for (int i = tid; i < BATCH; i += TPB)
            a += ((volatile float*)g_part)[i];
        #pragma unroll
        for (int o = 16; o; o >>= 1) a += __shfl_xor_sync(0xffffffffu, a, o);
        if ((tid & 31) == 0) s_red[tid >> 5] = a;
        __syncthreads();
        if (tid == 0) {
            float t = 0.0f;
            #pragma unroll
            for (int w = 0; w < TPB / 32; w++) t += s_red[w];
            loss_out[0] = t;
            g_ctr = 0;                           // reset for next replay
        }
    }
}

extern "C" void kernel_launch(void* const* d_in, const int* in_sizes, int n_in,
                              void* d_out, int out_size) {
    const float* features = (const float*)d_in[0];
    const int*   labels_w = (const int*)d_in[1];
    const float* centers  = (const float*)d_in[2];

    float* out = (float*)d_out;
    float* out_centers = out + ((size_t)out_size - NTOT);

    // Bulk copy ALL rows via the driver's tuned D2D path (explicitly allowed
    // in graph capture). Matched rows are overwritten by owner_kernel next.
    cudaMemcpyAsync(out_centers, centers, NTOT * sizeof(float),
                    cudaMemcpyDeviceToDevice);

    owner_kernel<<<BATCH, TPB>>>(features, centers, out_centers, out, labels_w);
}

// round 13
// speedup vs baseline: 1.6554x; 1.6554x over previous
#include <cuda_runtime.h>
#include <stdint.h>

#define NUM_CLASSES 10000
#define FEATURE_DIM 2048
#define BATCH 512
#define TPB 256
#define NTOT ((size_t)NUM_CLASSES * FEATURE_DIM)
#define BM_WORDS ((NUM_CLASSES + 31) / 32)   // 313
// ALPHA = 0.5 exactly -> powers of two via ldexpf

__device__ int          g_lab[BATCH];     // decoded labels
__device__ unsigned int g_bm[BM_WORDS];   // matched-class bitmap

// ---------------------------------------------------------------------------
// Init (1 block, 512 threads, minimal): zero loss, decode labels (int64 vs
// int32 probe), build matched bitmap. No count sweep, no worklist — with one
// block per class in the main kernel, ownership is structural.
// ---------------------------------------------------------------------------
__global__ void init_kernel(const int* __restrict__ labels_words,
                            float* __restrict__ loss_out) {
    __shared__ int s_not64;
    int tid = threadIdx.x;
    if (tid == 0) { s_not64 = 0; loss_out[0] = 0.0f; }
    if (tid < BM_WORDS) g_bm[tid] = 0u;              // words 0..311
    if (tid >= BATCH - (BM_WORDS - BATCH < 0 ? 0 : 0) && tid < BM_WORDS) {}
    if (tid + BATCH < BM_WORDS) g_bm[tid + BATCH] = 0u;  // (unreachable; BM_WORDS<512)
    __syncthreads();
    int lo = __ldg(labels_words + 2 * tid);
    int hi = __ldg(labels_words + 2 * tid + 1);
    // int64 hypothesis: every odd 32-bit word 0, every even word a valid id.
    if (hi != 0 || lo < 0 || lo >= NUM_CLASSES) s_not64 = 1;   // benign race
    __syncthreads();
    int lab = s_not64 ? __ldg(labels_words + tid) : lo;
    g_lab[tid] = lab;
    atomicOr(&g_bm[lab >> 5], 1u << (lab & 31));
}

// ---------------------------------------------------------------------------
// Main: one block per class r.
//  bitmap bit clear  -> copy row r (vectorized per MODE).
//  bitmap bit set    -> this block uniquely owns class r: collect matched batch
//    indices from g_lab, sort to batch order, apply the closed-form sequential
//    EMA  new_c = 2^-k*c + sum_r 2^-(k-r)*f_r  (ALPHA = 0.5) and accumulate the
//    class's MSE-loss partial (vs ORIGINAL center row) via one atomicAdd.
// MODE 0: dst rows 16B-aligned; MODE 1: dst base == 4 (mod 16) — output quads
// at drow+3+4j are aligned; the carried word comes from a scalar __ldg (L1-hit,
// no shfl dependency); MODE 2: scalar fallback.
// ---------------------------------------------------------------------------
template <int MODE>
__global__ void __launch_bounds__(TPB)
main_kernel(const float* __restrict__ features,
            const float* __restrict__ centers,
            float* __restrict__ out_centers,
            float* __restrict__ loss_out) {
    const int r   = blockIdx.x;
    const int tid = threadIdx.x;

    const float* srow = centers     + (size_t)r * FEATURE_DIM;
    float*       drow = out_centers + (size_t)r * FEATURE_DIM;

    const bool matched = (__ldg((const unsigned int*)g_bm + (r >> 5)) >> (r & 31)) & 1u;

    if (!matched) {
        // ---------------- copy path (>=9488 of 10000 rows) ----------------
        if (MODE == 0) {
            const float4* s4 = (const float4*)srow;
            float4*       d4 = (float4*)drow;
            #pragma unroll
            for (int s = 0; s < (FEATURE_DIM / 4) / TPB; s++) {
                int j = tid + s * TPB;
                d4[j] = __ldg(s4 + j);
            }
        } else if (MODE == 1) {
            // drow == 4 (mod 16): aligned output quads [3+4j .. 6+4j], j<511.
            if (tid < 3)  drow[tid] = __ldg(srow + tid);
            if (tid == 3) drow[FEATURE_DIM - 1] = __ldg(srow + FEATURE_DIM - 1);
            #pragma unroll
            for (int s = 0; s < 2; s++) {
                int j = tid + s * TPB;
                if (j < (FEATURE_DIM / 4) - 1) {
                    float4 q = __ldg((const float4*)srow + j + 1);
                    float  w = __ldg(srow + 4 * j + 3);     // L1-hit scalar
                    *(float4*)(drow + 3 + 4 * j) = make_float4(w, q.x, q.y, q.z);
                }
            }
        } else {
            #pragma unroll
            for (int s = 0; s < FEATURE_DIM / TPB; s++) {
                int c = tid + s * TPB;
                drow[c] = __ldg(srow + c);
            }
        }
        return;
    }

    // ---------------- owner path (this block uniquely owns class r) ----------
    __shared__ int   s_match[BATCH];
    __shared__ float s_w[BATCH];
    __shared__ int   s_cnt;
    __shared__ float s_red[TPB / 32];

    if (tid == 0) s_cnt = 0;
    __syncthreads();
    for (int j = tid; j < BATCH; j += TPB)
        if (__ldg((const int*)g_lab + j) == r)
            s_match[atomicAdd(&s_cnt, 1)] = j;
    __syncthreads();
    const int k = s_cnt;
    if (tid == 0) {   // restore batch order + EMA weights
        for (int a = 1; a < k; a++) {
            int v = s_match[a], c = a - 1;
            while (c >= 0 && s_match[c] > v) { s_match[c + 1] = s_match[c]; c--; }
            s_match[c + 1] = v;
        }
        for (int q = 0; q < k; q++) s_w[q] = ldexpf(1.0f, -(k - q));
    }
    __syncthreads();

    const float decay = ldexpf(1.0f, -k);
    float acc = 0.0f;
    #pragma unroll
    for (int s = 0; s < FEATURE_DIM / TPB; s++) {
        int c = tid + s * TPB;
        float cv = __ldg(srow + c);
        float nv = cv * decay;
        for (int q = 0; q < k; q++) {
            float f = __ldg(features + (size_t)s_match[q] * FEATURE_DIM + c);
            nv = fmaf(s_w[q], f, nv);
            float d = f - cv;                    // loss vs ORIGINAL center
            acc = fmaf(d, d, acc);
        }
        drow[c] = nv;
    }

    #pragma unroll
    for (int o = 16; o; o >>= 1) acc += __shfl_xor_sync(0xffffffffu, acc, o);
    if ((tid & 31) == 0) s_red[tid >> 5] = acc;
    __syncthreads();
    if (tid == 0) {
        float t = 0.0f;
        #pragma unroll
        for (int w = 0; w < TPB / 32; w++) t += s_red[w];
        atomicAdd(loss_out, t * (1.0f / ((float)BATCH * (float)FEATURE_DIM)));
    }
}

extern "C" void kernel_launch(void* const* d_in, const int* in_sizes, int n_in,
                              void* d_out, int out_size) {
    const float* features = (const float*)d_in[0];
    const int*   labels_w = (const int*)d_in[1];
    const float* centers  = (const float*)d_in[2];

    float* out = (float*)d_out;
    float* out_centers = out + ((size_t)out_size - NTOT);

    init_kernel<<<1, BATCH>>>(labels_w, out);

    uintptr_t a = (uintptr_t)out_centers;
    if ((a & 15) == 0)
        main_kernel<0><<<NUM_CLASSES, TPB>>>(features, centers, out_centers, out);
    else if ((a & 15) == 4)
        main_kernel<1><<<NUM_CLASSES, TPB>>>(features, centers, out_centers, out);
    else
        main_kernel<2><<<NUM_CLASSES, TPB>>>(features, centers, out_centers, out);
}

// round 15
// speedup vs baseline: 1.8383x; 1.1105x over previous
#include <cuda_runtime.h>
#include <stdint.h>

#define NUM_CLASSES 10000
#define FEATURE_DIM 2048
#define BATCH 512
#define TPB 512
#define NTOT ((size_t)NUM_CLASSES * FEATURE_DIM)
// ALPHA = 0.5 exactly -> powers of two via ldexpf

__device__ int g_lab[BATCH];   // decoded labels

// ---------------------------------------------------------------------------
// Lean init (1 block, 512 threads): zero loss scalar + decode labels
// (int64 vs int32 probe). Nothing else — main kernel scans labels itself.
// ---------------------------------------------------------------------------
__global__ void init_kernel(const int* __restrict__ labels_words,
                            float* __restrict__ loss_out) {
    __shared__ int s_not64;
    int tid = threadIdx.x;
    if (tid == 0) { s_not64 = 0; loss_out[0] = 0.0f; }
    __syncthreads();
    int lo = __ldg(labels_words + 2 * tid);
    int hi = __ldg(labels_words + 2 * tid + 1);
    // int64 hypothesis: every odd 32-bit word 0, every even word a valid id.
    if (hi != 0 || lo < 0 || lo >= NUM_CLASSES) s_not64 = 1;   // benign race
    __syncthreads();
    g_lab[tid] = s_not64 ? __ldg(labels_words + tid) : lo;
}

// ---------------------------------------------------------------------------
// Main: one block (512 threads) per class row. Scan the 512 decoded labels in
// ONE pass; k==0 -> scalar row copy (best-measured copy form); k>0 -> this
// block uniquely owns class r: sort matches to batch order and apply the
// closed-form sequential EMA  new_c = 2^-k*c + sum_q 2^-(k-q)*f_q  (ALPHA=0.5),
// accumulating the class's MSE-loss partial vs the ORIGINAL center row.
// ---------------------------------------------------------------------------
__global__ void __launch_bounds__(TPB)
center_kernel(const float* __restrict__ features,
              const float* __restrict__ centers,
              float* __restrict__ out_centers,
              float* __restrict__ loss_out) {
    __shared__ int   s_match[BATCH];
    __shared__ float s_w[BATCH];
    __shared__ int   s_cnt;
    __shared__ float s_red[TPB / 32];

    const int r   = blockIdx.x;
    const int tid = threadIdx.x;

    if (tid == 0) s_cnt = 0;
    __syncthreads();

    // One-pass match scan (TPB == BATCH).
    if (g_lab[tid] == r) {
        int p = atomicAdd(&s_cnt, 1);
        s_match[p] = tid;
    }
    __syncthreads();
    const int k = s_cnt;

    const float* crow = centers     + (size_t)r * FEATURE_DIM;
    float*       drow = out_centers + (size_t)r * FEATURE_DIM;

    if (k == 0) {
        // Scalar coalesced copy — best-measured form (beats float4 variants).
        #pragma unroll
        for (int s = 0; s < FEATURE_DIM / TPB; s++) {
            int c = tid + s * TPB;
            drow[c] = __ldg(crow + c);
        }
        return;
    }

    // Restore batch order + precompute EMA weights.
    if (tid == 0) {
        for (int a = 1; a < k; a++) {
            int v = s_match[a], b = a - 1;
            while (b >= 0 && s_match[b] > v) { s_match[b + 1] = s_match[b]; b--; }
            s_match[b + 1] = v;
        }
        for (int q = 0; q < k; q++) s_w[q] = ldexpf(1.0f, -(k - q));
    }
    __syncthreads();

    const float decay = ldexpf(1.0f, -k);
    float acc = 0.0f;

    #pragma unroll
    for (int s = 0; s < FEATURE_DIM / TPB; s++) {
        int c = tid + s * TPB;
        float cv = __ldg(crow + c);
        float nv = cv * decay;
        for (int q = 0; q < k; q++) {
            float f = __ldg(features + (size_t)s_match[q] * FEATURE_DIM + c);
            nv = fmaf(s_w[q], f, nv);
            float d = f - cv;                  // loss vs ORIGINAL center row
            acc = fmaf(d, d, acc);
        }
        drow[c] = nv;
    }

    // Block-reduce the loss partial; one atomicAdd per matched class.
    #pragma unroll
    for (int o = 16; o; o >>= 1) acc += __shfl_xor_sync(0xffffffffu, acc, o);
    if ((tid & 31) == 0) s_red[tid >> 5] = acc;
    __syncthreads();
    if (tid == 0) {
        float t = 0.0f;
        #pragma unroll
        for (int w = 0; w < TPB / 32; w++) t += s_red[w];
        atomicAdd(loss_out, t * (1.0f / ((float)BATCH * (float)FEATURE_DIM)));
    }
}

extern "C" void kernel_launch(void* const* d_in, const int* in_sizes, int n_in,
                              void* d_out, int out_size) {
    const float* features = (const float*)d_in[0];
    const int*   labels_w = (const int*)d_in[1];
    const float* centers  = (const float*)d_in[2];

    float* out = (float*)d_out;
    float* out_centers = out + ((size_t)out_size - NTOT);

    init_kernel<<<1, BATCH>>>(labels_w, out);
    center_kernel<<<NUM_CLASSES, TPB>>>(features, centers, out_centers, out);
}